// round 7
// baseline (speedup 1.0000x reference)
#include <cuda_runtime.h>
#include <stdint.h>
#include <math.h>

#define N_ROWS 16384
#define K_EMB  8192
#define D_EMB  64
#define TOPK   10
#define CPT    12               // candidates kept per thread-list (slack over 10)
#define CAND   48               // 4 quad-threads x 12 per row

#define MTILE  128              // rows per CTA (stage 1)
#define NTILE  128              // codewords per tile
#define NT     (K_EMB/NTILE)    // 64
#define GRID1  (N_ROWS/MTILE)   // 128

#define RPB2   8                // rows per block (stage 2), 1 warp per row
#define GRID2  (N_ROWS/RPB2)    // 2048

// output layout (float32, reference return order)
#define OFF_LOSS  1048576
#define OFF_IDX   (OFF_LOSS + 1)
#define OFF_MIND  (OFF_IDX + N_ROWS)
#define OFF_PERP  (OFF_MIND + N_ROWS)

// device scratch
__device__ float g_esq[K_EMB];
__device__ int   g_counts[K_EMB];
__device__ int   g_cand[(size_t)N_ROWS * CAND];
__device__ float g_losspart[GRID2];
__device__ float g_validpart[GRID2];

__device__ __forceinline__ uint32_t tf32_bits(float x) {
    uint32_t u; asm("cvt.rna.tf32.f32 %0, %1;" : "=r"(u) : "f"(x)); return u;
}
__device__ __forceinline__ float tf32_val(float x) {
    return __uint_as_float(tf32_bits(x));
}
__device__ __forceinline__ void mma_tf32(float &c0, float &c1, float &c2, float &c3,
                                         uint32_t a0, uint32_t a1, uint32_t a2, uint32_t a3,
                                         uint32_t b0, uint32_t b1) {
    asm volatile(
        "mma.sync.aligned.m16n8k8.row.col.f32.tf32.tf32.f32 "
        "{%0,%1,%2,%3}, {%4,%5,%6,%7}, {%8,%9}, {%0,%1,%2,%3};"
        : "+f"(c0), "+f"(c1), "+f"(c2), "+f"(c3)
        : "r"(a0), "r"(a1), "r"(a2), "r"(a3), "r"(b0), "r"(b1));
}

// ---------------------------------------------------------------------------
// prep: exact per-codeword squared norms + zero histogram
// ---------------------------------------------------------------------------
__global__ __launch_bounds__(256) void vq_prep(const float* __restrict__ cb) {
    int k = blockIdx.x * 32 + (threadIdx.x >> 3);
    int l = threadIdx.x & 7;
    const float4* e4 = reinterpret_cast<const float4*>(cb + (size_t)k * D_EMB);
    float4 a = e4[l * 2], b = e4[l * 2 + 1];
    float s = 0.f;
    s = fmaf(a.x, a.x, s); s = fmaf(a.y, a.y, s);
    s = fmaf(a.z, a.z, s); s = fmaf(a.w, a.w, s);
    s = fmaf(b.x, b.x, s); s = fmaf(b.y, b.y, s);
    s = fmaf(b.z, b.z, s); s = fmaf(b.w, b.w, s);
    s += __shfl_xor_sync(0xffffffffu, s, 1);
    s += __shfl_xor_sync(0xffffffffu, s, 2);
    s += __shfl_xor_sync(0xffffffffu, s, 4);
    if (l == 0) g_esq[k] = s;
    if (threadIdx.x < 32) g_counts[blockIdx.x * 32 + threadIdx.x] = 0;
}

// ---------------------------------------------------------------------------
// stage 1: TF32 mma.sync approx scores; per-thread top-12 over owned columns.
// CTA = 256 threads = 8 warps; warp w owns rows [blk*128 + w*16, +16).
// Thread (lane) fragment rows: r0 = base + lane/4, r0+8. Columns owned per
// thread: {n0 + 2*(lane%4), +1} per n8-chunk -> quad-disjoint cover of 8192.
// smem B layout: float2 sB[(s*128+n)*4 + kk] = (B[s*8+kk][n], B[s*8+4+kk][n])
// -> each mma's (b0,b1) is one conflict-free LDS.64.
// ---------------------------------------------------------------------------
#define INSERT12(td, ti, sc, ix)                                     \
    if ((sc) < td[CPT - 1]) {                                        \
        td[CPT - 1] = (sc); ti[CPT - 1] = (ix);                      \
        _Pragma("unroll")                                            \
        for (int _j = CPT - 1; _j > 0; --_j) {                       \
            if (td[_j] < td[_j - 1]) {                               \
                float _tf = td[_j]; td[_j] = td[_j-1]; td[_j-1] = _tf; \
                int   _tg = ti[_j]; ti[_j] = ti[_j-1]; ti[_j-1] = _tg; \
            } else break;                                            \
        }                                                            \
    }

__global__ __launch_bounds__(256, 1) void vq_topc(const float* __restrict__ inp,
                                                  const float* __restrict__ cb) {
    __shared__ __align__(16) float sB[8 * 128 * 8];   // 32 KB
    __shared__ float s_esq[NTILE];

    const int tid  = threadIdx.x;
    const int lane = tid & 31, wid = tid >> 5;
    const int q    = lane & 3, rq = lane >> 2;
    const int rowbase = blockIdx.x * MTILE + wid * 16;
    const int r0 = rowbase + rq;                       // and r0+8

    // A fragments: tf32(-2x), persistent
    uint32_t A[8][4];
    {
        const float* x0p = inp + (size_t)r0 * D_EMB;
        const float* x1p = inp + (size_t)(r0 + 8) * D_EMB;
        #pragma unroll
        for (int s = 0; s < 8; s++) {
            A[s][0] = tf32_bits(-2.0f * x0p[s * 8 + q]);
            A[s][1] = tf32_bits(-2.0f * x1p[s * 8 + q]);
            A[s][2] = tf32_bits(-2.0f * x0p[s * 8 + 4 + q]);
            A[s][3] = tf32_bits(-2.0f * x1p[s * 8 + 4 + q]);
        }
    }

    float td0[CPT], td1[CPT]; int ti0[CPT], ti1[CPT];
    #pragma unroll
    for (int j = 0; j < CPT; j++) {
        td0[j] = __int_as_float(0x7f800000); ti0[j] = 0;
        td1[j] = __int_as_float(0x7f800000); ti1[j] = 0;
    }

    const float4* cb4 = reinterpret_cast<const float4*>(cb);
    const float2* sB2 = reinterpret_cast<const float2*>(sB);

    for (int t = 0; t < NT; t++) {
        __syncthreads();
        const int cw0 = t * NTILE;
        // stage B tile (128 codewords x 64 k), tf32-converted, pair-interleaved
        #pragma unroll
        for (int it = 0; it < 8; it++) {
            int li = tid + 256 * it;          // 0..2047
            int n = li >> 4, qq = li & 15;    // qq: float4 index (k = 4qq..4qq+3)
            float4 v = cb4[(size_t)(cw0 + n) * 16 + qq];
            int s = qq >> 1, h = qq & 1;      // h: 0 -> b0 slot, 1 -> b1 slot
            float* base = sB + (s * 128 + n) * 8 + h;
            base[0] = tf32_val(v.x); base[2] = tf32_val(v.y);
            base[4] = tf32_val(v.z); base[6] = tf32_val(v.w);
        }
        if (tid < NTILE) s_esq[tid] = g_esq[cw0 + tid];
        __syncthreads();

        #pragma unroll 2
        for (int ch = 0; ch < 16; ch++) {
            const int n0 = ch * 8;
            float c0 = 0.f, c1 = 0.f, c2 = 0.f, c3 = 0.f;
            const float2* bp = sB2 + (n0 + rq) * 4 + q;
            #pragma unroll
            for (int s = 0; s < 8; s++) {
                float2 b = bp[s * 512];
                mma_tf32(c0, c1, c2, c3,
                         A[s][0], A[s][1], A[s][2], A[s][3],
                         __float_as_uint(b.x), __float_as_uint(b.y));
            }
            // approx score (per-row constant xsq omitted; ranking unaffected)
            float e0 = s_esq[n0 + 2 * q], e1 = s_esq[n0 + 2 * q + 1];
            int ib = cw0 + n0 + 2 * q;
            float s0 = e0 + c0, s1 = e1 + c1;    // row r0
            float s2 = e0 + c2, s3 = e1 + c3;    // row r0+8
            INSERT12(td0, ti0, s0, ib);
            INSERT12(td0, ti0, s1, ib + 1);
            INSERT12(td1, ti1, s2, ib);
            INSERT12(td1, ti1, s3, ib + 1);
        }
    }

    int* cp0 = g_cand + (size_t)r0 * CAND + q * CPT;
    int* cp1 = g_cand + (size_t)(r0 + 8) * CAND + q * CPT;
    #pragma unroll
    for (int j = 0; j < CPT; j++) { cp0[j] = ti0[j]; cp1[j] = ti1[j]; }
}

// ---------------------------------------------------------------------------
// stage 2: exact fp32 rescore of 48 candidates/row, stable top-10, gumbel,
// outputs + partial losses. 256 threads = 8 warps = 8 rows per block.
// ---------------------------------------------------------------------------
__global__ __launch_bounds__(256) void vq_rescore(const float* __restrict__ inp,
                                                  const float* __restrict__ cb,
                                                  const float* __restrict__ gum,
                                                  float* __restrict__ out) {
    __shared__ float sx[RPB2][D_EMB];
    __shared__ float sA[RPB2], sB[RPB2];

    const int tid = threadIdx.x;
    const int wid = tid >> 5, lid = tid & 31;
    const int row = blockIdx.x * RPB2 + wid;

    // stage x rows into smem (coalesced)
    reinterpret_cast<float2*>(&sx[0][0])[tid] =
        reinterpret_cast<const float2*>(inp + (size_t)blockIdx.x * RPB2 * D_EMB)[tid];
    __syncthreads();

    // full row x in registers (broadcast LDS) + exact xsq
    float4 xr[16];
    const float4* sx4 = reinterpret_cast<const float4*>(&sx[wid][0]);
    #pragma unroll
    for (int i = 0; i < 16; i++) xr[i] = sx4[i];
    float xsq = 0.f;
    #pragma unroll
    for (int i = 0; i < 16; i++) {
        xsq = fmaf(xr[i].x, xr[i].x, xsq); xsq = fmaf(xr[i].y, xr[i].y, xsq);
        xsq = fmaf(xr[i].z, xr[i].z, xsq); xsq = fmaf(xr[i].w, xr[i].w, xsq);
    }

    // two candidate slots per lane: lid and 32+lid (latter valid for lid<16)
    const int* cr = g_cand + (size_t)row * CAND;
    int   i0 = cr[lid];
    int   i1 = (lid < CAND - 32) ? cr[32 + lid] : 0x7fffffff;
    float d0, d1 = __int_as_float(0x7f800000);
    {
        const float4* e4 = reinterpret_cast<const float4*>(cb + (size_t)i0 * D_EMB);
        float dot = 0.f;
        #pragma unroll
        for (int i = 0; i < 16; i++) {
            float4 e = e4[i];
            dot = fmaf(xr[i].x, e.x, dot); dot = fmaf(xr[i].y, e.y, dot);
            dot = fmaf(xr[i].z, e.z, dot); dot = fmaf(xr[i].w, e.w, dot);
        }
        d0 = (xsq + g_esq[i0]) - 2.0f * dot;
    }
    if (lid < CAND - 32) {
        const float4* e4 = reinterpret_cast<const float4*>(cb + (size_t)i1 * D_EMB);
        float dot = 0.f;
        #pragma unroll
        for (int i = 0; i < 16; i++) {
            float4 e = e4[i];
            dot = fmaf(xr[i].x, e.x, dot); dot = fmaf(xr[i].y, e.y, dot);
            dot = fmaf(xr[i].z, e.z, dot); dot = fmaf(xr[i].w, e.w, dot);
        }
        d1 = (xsq + g_esq[i1]) - 2.0f * dot;
    }

    // stable all-pairs rank by (d asc, idx asc); candidate indices are distinct
    int rank0 = 0, rank1 = 0;
    #pragma unroll 8
    for (int s = 0; s < 32; s++) {
        float dA = __shfl_sync(0xffffffffu, d0, s); int iA = __shfl_sync(0xffffffffu, i0, s);
        float dB = __shfl_sync(0xffffffffu, d1, s); int iB = __shfl_sync(0xffffffffu, i1, s);
        rank0 += (dA < d0) || (dA == d0 && iA < i0);
        rank0 += (dB < d0) || (dB == d0 && iB < i0);
        rank1 += (dA < d1) || (dA == d1 && iA < i1);
        rank1 += (dB < d1) || (dB == d1 && iB < i1);
    }

    // gather sorted top-10 to all lanes
    float topd[TOPK]; int topi[TOPK];
    #pragma unroll
    for (int j = 0; j < TOPK; j++) {
        unsigned m0 = __ballot_sync(0xffffffffu, rank0 == j);
        unsigned m1 = __ballot_sync(0xffffffffu, rank1 == j);
        int s0 = (__ffs(m0) - 1) & 31;
        int s1 = (__ffs(m1) - 1) & 31;
        float dv0 = __shfl_sync(0xffffffffu, d0, s0);
        int   iv0 = __shfl_sync(0xffffffffu, i0, s0);
        float dv1 = __shfl_sync(0xffffffffu, d1, s1);
        int   iv1 = __shfl_sync(0xffffffffu, i1, s1);
        topd[j] = m0 ? dv0 : dv1;
        topi[j] = m0 ? iv0 : iv1;
    }

    // gumbel-max over slots (strict > keeps first on ties, matches argmax)
    float gv = (lid < TOPK) ? gum[(size_t)row * TOPK + lid] : 0.f;
    float best = -__int_as_float(0x7f800000); int jb = 0;
    #pragma unroll
    for (int j = 0; j < TOPK; j++) {
        float v = __shfl_sync(0xffffffffu, gv, j) - topd[j];
        if (v > best) { best = v; jb = j; }
    }
    const int   idx  = topi[jb];
    const float mind = topd[jb];
    const bool  valid = (xsq > 1e-12f);   // norm > 1e-6
    const float vm = valid ? 1.0f : 0.0f;

    // quantized_st row: x + (q*vm - x); 2 elements per lane
    const float2* q2 = reinterpret_cast<const float2*>(cb + (size_t)idx * D_EMB);
    float2 qv = q2[lid];
    float2 x2 = reinterpret_cast<const float2*>(&sx[wid][0])[lid];
    float e0 = qv.x - x2.x, e1 = qv.y - x2.y;
    float ss = fmaf(e0, e0, e1 * e1);
    float2 o;
    o.x = x2.x + (qv.x * vm - x2.x);
    o.y = x2.y + (qv.y * vm - x2.y);
    reinterpret_cast<float2*>(out + (size_t)row * D_EMB)[lid] = o;

    ss += __shfl_xor_sync(0xffffffffu, ss, 16);
    ss += __shfl_xor_sync(0xffffffffu, ss, 8);
    ss += __shfl_xor_sync(0xffffffffu, ss, 4);
    ss += __shfl_xor_sync(0xffffffffu, ss, 2);
    ss += __shfl_xor_sync(0xffffffffu, ss, 1);
    ss *= vm;

    if (lid == 0) {
        out[OFF_IDX  + row] = valid ? (float)idx : 0.0f;
        out[OFF_MIND + row] = valid ? mind : 0.0f;
        if (valid) atomicAdd(&g_counts[idx], 1);
        sA[wid] = ss; sB[wid] = vm;
    }
    __syncthreads();
    if (tid == 0) {
        float a = 0.f, b = 0.f;
        #pragma unroll
        for (int w = 0; w < RPB2; w++) { a += sA[w]; b += sB[w]; }
        g_losspart[blockIdx.x] = a;
        g_validpart[blockIdx.x] = b;
    }
}

// ---------------------------------------------------------------------------
// final: deterministic reductions -> total_loss, perplexity
// ---------------------------------------------------------------------------
__global__ void vq_final(float* __restrict__ out) {
    __shared__ float sA[256], sB[256];
    int tid = threadIdx.x;
    float a = 0.f, b = 0.f;
    for (int i = tid; i < GRID2; i += 256) { a += g_losspart[i]; b += g_validpart[i]; }
    sA[tid] = a; sB[tid] = b;
    __syncthreads();
    for (int st = 128; st > 0; st >>= 1) {
        if (tid < st) { sA[tid] += sA[tid + st]; sB[tid] += sB[tid + st]; }
        __syncthreads();
    }
    float n_valid = fmaxf(sB[0], 1.0f);
    float loss_vq = sA[0] / (n_valid * (float)D_EMB);
    __syncthreads();

    float local = 0.f;
    for (int k = tid; k < K_EMB; k += 256) {
        float p = (float)g_counts[k] / n_valid;
        local += p * logf(p + 1e-10f);
    }
    sA[tid] = local;
    __syncthreads();
    for (int st = 128; st > 0; st >>= 1) {
        if (tid < st) sA[tid] += sA[tid + st];
        __syncthreads();
    }
    if (tid == 0) {
        float perplexity = expf(-sA[0]);
        float ploss = -logf(perplexity + 1e-10f);
        out[OFF_LOSS] = loss_vq + 0.01f * ploss;
        out[OFF_PERP] = perplexity;
    }
}

extern "C" void kernel_launch(void* const* d_in, const int* in_sizes, int n_in,
                              void* d_out, int out_size) {
    (void)in_sizes; (void)n_in; (void)out_size;
    const float* inp = (const float*)d_in[0];
    const float* cb  = (const float*)d_in[1];
    const float* gum = (const float*)d_in[2];
    float* out = (float*)d_out;

    vq_prep<<<K_EMB / 32, 256>>>(cb);
    vq_topc<<<GRID1, 256>>>(inp, cb);
    vq_rescore<<<GRID2, 256>>>(inp, cb, gum, out);
    vq_final<<<1, 256>>>(out);
}

// round 9
// speedup vs baseline: 1.1543x; 1.1543x over previous
#include <cuda_runtime.h>
#include <cuda_bf16.h>
#include <stdint.h>
#include <math.h>

#define N_ROWS 16384
#define K_EMB  8192
#define D_EMB  64
#define TOPK   10
#define CPT    12               // candidates kept per thread-list (slack over 10)
#define CAND   48               // 4 quad-threads x 12 per row

#define MTILE  128              // rows per CTA (stage 1)
#define NTILE  128              // codewords per tile
#define NT     (K_EMB/NTILE)    // 64
#define GRID1  (N_ROWS/MTILE)   // 128

#define RPB2   8                // rows per block (stage 2), 1 warp per row
#define GRID2  (N_ROWS/RPB2)    // 2048

// output layout (float32, reference return order)
#define OFF_LOSS  1048576
#define OFF_IDX   (OFF_LOSS + 1)
#define OFF_MIND  (OFF_IDX + N_ROWS)
#define OFF_PERP  (OFF_MIND + N_ROWS)

// device scratch
__device__ float    g_esq[K_EMB];
__device__ int      g_counts[K_EMB];
__device__ int      g_cand[(size_t)N_ROWS * CAND];
__device__ float    g_losspart[GRID2];
__device__ float    g_validpart[GRID2];
// bf16 codebook, mma-fragment order: u32 idx = ((t*4+s)*128 + nloc)*8 + q*2 + h
// u32 = { lo = bf16(cb[n][16s+8h+2q]), hi = bf16(cb[n][16s+8h+2q+1]) }
__device__ uint32_t g_cbf[(size_t)K_EMB * (D_EMB / 2)];

__device__ __forceinline__ uint32_t pack_bf16(float lo, float hi) {
    __nv_bfloat162 v = __floats2bfloat162_rn(lo, hi);   // x=lo, y=hi
    return *reinterpret_cast<uint32_t*>(&v);
}
__device__ __forceinline__ void mma_bf16(float &c0, float &c1, float &c2, float &c3,
                                         uint32_t a0, uint32_t a1, uint32_t a2, uint32_t a3,
                                         uint32_t b0, uint32_t b1) {
    asm volatile(
        "mma.sync.aligned.m16n8k16.row.col.f32.bf16.bf16.f32 "
        "{%0,%1,%2,%3}, {%4,%5,%6,%7}, {%8,%9}, {%0,%1,%2,%3};"
        : "+f"(c0), "+f"(c1), "+f"(c2), "+f"(c3)
        : "r"(a0), "r"(a1), "r"(a2), "r"(a3), "r"(b0), "r"(b1));
}

// ---------------------------------------------------------------------------
// prep: exact per-codeword squared norms + zero histogram
// ---------------------------------------------------------------------------
__global__ __launch_bounds__(256) void vq_prep(const float* __restrict__ cb) {
    int k = blockIdx.x * 32 + (threadIdx.x >> 3);
    int l = threadIdx.x & 7;
    const float4* e4 = reinterpret_cast<const float4*>(cb + (size_t)k * D_EMB);
    float4 a = e4[l * 2], b = e4[l * 2 + 1];
    float s = 0.f;
    s = fmaf(a.x, a.x, s); s = fmaf(a.y, a.y, s);
    s = fmaf(a.z, a.z, s); s = fmaf(a.w, a.w, s);
    s = fmaf(b.x, b.x, s); s = fmaf(b.y, b.y, s);
    s = fmaf(b.z, b.z, s); s = fmaf(b.w, b.w, s);
    s += __shfl_xor_sync(0xffffffffu, s, 1);
    s += __shfl_xor_sync(0xffffffffu, s, 2);
    s += __shfl_xor_sync(0xffffffffu, s, 4);
    if (l == 0) g_esq[k] = s;
    if (threadIdx.x < 32) g_counts[blockIdx.x * 32 + threadIdx.x] = 0;
}

// ---------------------------------------------------------------------------
// pack: fp32 codebook -> bf16 fragment-ordered global array (one u32/thread)
// ---------------------------------------------------------------------------
__global__ __launch_bounds__(256) void vq_pack(const float* __restrict__ cb) {
    int gidx = blockIdx.x * 256 + threadIdx.x;       // 0 .. 262143
    int r    = gidx & 7;                             // q*2 + h
    int nl   = (gidx >> 3) & 127;
    int sec  = gidx >> 10;                           // t*4 + s
    int t    = sec >> 2, s = sec & 3;
    int q = r >> 1, h = r & 1;
    int n = t * 128 + nl;
    int k0 = 16 * s + 8 * h + 2 * q;
    float2 v = *reinterpret_cast<const float2*>(cb + (size_t)n * D_EMB + k0);
    g_cbf[gidx] = pack_bf16(v.x, v.y);
}

// ---------------------------------------------------------------------------
// stage 1: bf16 mma.sync approx scores, NO smem, b operands via coalesced
// LDG.64 from g_cbf. CTA = 256 threads = 8 warps; warp w owns rows
// [blk*128 + w*16, +16). Thread handles rows r0=base+lane/4 and r0+8;
// owns cols {n0+2q, n0+2q+1} per n8 chunk (quad-disjoint over 8192).
// A = bf16(-2x) fragments persistent in registers.
// ---------------------------------------------------------------------------
#define INSERT12(td, ti, sc, ix)                                     \
    if ((sc) < td[CPT - 1]) {                                        \
        td[CPT - 1] = (sc); ti[CPT - 1] = (ix);                      \
        _Pragma("unroll")                                            \
        for (int _j = CPT - 1; _j > 0; --_j) {                       \
            if (td[_j] < td[_j - 1]) {                               \
                float _tf = td[_j]; td[_j] = td[_j-1]; td[_j-1] = _tf; \
                int   _tg = ti[_j]; ti[_j] = ti[_j-1]; ti[_j-1] = _tg; \
            } else break;                                            \
        }                                                            \
    }

__global__ __launch_bounds__(256, 1) void vq_topc(const float* __restrict__ inp) {
    const int tid  = threadIdx.x;
    const int lane = tid & 31, wid = tid >> 5;
    const int q    = lane & 3, rq = lane >> 2;
    const int r0   = blockIdx.x * MTILE + wid * 16 + rq;   // and r0+8

    // A fragments: bf16(-2x), persistent. a0:(r0, 2q), a1:(r0+8, 2q),
    // a2:(r0, 2q+8), a3:(r0+8, 2q+8) for each 16-wide kstep s.
    uint32_t A[4][4];
    {
        const float* x0p = inp + (size_t)r0 * D_EMB;
        const float* x1p = inp + (size_t)(r0 + 8) * D_EMB;
        #pragma unroll
        for (int s = 0; s < 4; s++) {
            float2 p;
            p = *reinterpret_cast<const float2*>(x0p + 16 * s + 2 * q);
            A[s][0] = pack_bf16(-2.0f * p.x, -2.0f * p.y);
            p = *reinterpret_cast<const float2*>(x1p + 16 * s + 2 * q);
            A[s][1] = pack_bf16(-2.0f * p.x, -2.0f * p.y);
            p = *reinterpret_cast<const float2*>(x0p + 16 * s + 8 + 2 * q);
            A[s][2] = pack_bf16(-2.0f * p.x, -2.0f * p.y);
            p = *reinterpret_cast<const float2*>(x1p + 16 * s + 8 + 2 * q);
            A[s][3] = pack_bf16(-2.0f * p.x, -2.0f * p.y);
        }
    }

    float td0[CPT], td1[CPT]; int ti0[CPT], ti1[CPT];
    #pragma unroll
    for (int j = 0; j < CPT; j++) {
        td0[j] = __int_as_float(0x7f800000); ti0[j] = 0;
        td1[j] = __int_as_float(0x7f800000); ti1[j] = 0;
    }

    const uint2* gb = reinterpret_cast<const uint2*>(g_cbf);

    for (int t = 0; t < NT; t++) {
        // per-s section base, uint2 units: (t*4+s)*128*4
        const uint2* bt = gb + (size_t)t * 4 * 128 * 4;
        const float2* ep = reinterpret_cast<const float2*>(g_esq + t * NTILE);

        #pragma unroll 2
        for (int ch = 0; ch < 16; ch++) {
            const int n0 = ch * 8;
            float c0 = 0.f, c1 = 0.f, c2 = 0.f, c3 = 0.f;
            #pragma unroll
            for (int s = 0; s < 4; s++) {
                uint2 b = __ldg(&bt[(s * 128 + n0 + rq) * 4 + q]);
                mma_bf16(c0, c1, c2, c3,
                         A[s][0], A[s][1], A[s][2], A[s][3], b.x, b.y);
            }
            float2 e = __ldg(&ep[ch * 4 + q]);        // esq[n0+2q], esq[n0+2q+1]
            int ib = t * NTILE + n0 + 2 * q;
            INSERT12(td0, ti0, e.x + c0, ib);         // row r0
            INSERT12(td0, ti0, e.y + c1, ib + 1);
            INSERT12(td1, ti1, e.x + c2, ib);         // row r0+8
            INSERT12(td1, ti1, e.y + c3, ib + 1);
        }
    }

    int* cp0 = g_cand + (size_t)r0 * CAND + q * CPT;
    int* cp1 = g_cand + (size_t)(r0 + 8) * CAND + q * CPT;
    #pragma unroll
    for (int j = 0; j < CPT; j++) { cp0[j] = ti0[j]; cp1[j] = ti1[j]; }
}

// ---------------------------------------------------------------------------
// stage 2: exact fp32 rescore of 48 candidates/row, stable top-10, gumbel,
// outputs + partial losses. 256 threads = 8 warps = 8 rows per block.
// ---------------------------------------------------------------------------
__global__ __launch_bounds__(256) void vq_rescore(const float* __restrict__ inp,
                                                  const float* __restrict__ cb,
                                                  const float* __restrict__ gum,
                                                  float* __restrict__ out) {
    __shared__ float sx[RPB2][D_EMB];
    __shared__ float sA[RPB2], sB[RPB2];

    const int tid = threadIdx.x;
    const int wid = tid >> 5, lid = tid & 31;
    const int row = blockIdx.x * RPB2 + wid;

    reinterpret_cast<float2*>(&sx[0][0])[tid] =
        reinterpret_cast<const float2*>(inp + (size_t)blockIdx.x * RPB2 * D_EMB)[tid];
    __syncthreads();

    float4 xr[16];
    const float4* sx4 = reinterpret_cast<const float4*>(&sx[wid][0]);
    #pragma unroll
    for (int i = 0; i < 16; i++) xr[i] = sx4[i];
    float xsq = 0.f;
    #pragma unroll
    for (int i = 0; i < 16; i++) {
        xsq = fmaf(xr[i].x, xr[i].x, xsq); xsq = fmaf(xr[i].y, xr[i].y, xsq);
        xsq = fmaf(xr[i].z, xr[i].z, xsq); xsq = fmaf(xr[i].w, xr[i].w, xsq);
    }

    const int* cr = g_cand + (size_t)row * CAND;
    int   i0 = cr[lid];
    int   i1 = (lid < CAND - 32) ? cr[32 + lid] : 0x7fffffff;
    float d0, d1 = __int_as_float(0x7f800000);
    {
        const float4* e4 = reinterpret_cast<const float4*>(cb + (size_t)i0 * D_EMB);
        float dot = 0.f;
        #pragma unroll
        for (int i = 0; i < 16; i++) {
            float4 e = e4[i];
            dot = fmaf(xr[i].x, e.x, dot); dot = fmaf(xr[i].y, e.y, dot);
            dot = fmaf(xr[i].z, e.z, dot); dot = fmaf(xr[i].w, e.w, dot);
        }
        d0 = (xsq + g_esq[i0]) - 2.0f * dot;
    }
    if (lid < CAND - 32) {
        const float4* e4 = reinterpret_cast<const float4*>(cb + (size_t)i1 * D_EMB);
        float dot = 0.f;
        #pragma unroll
        for (int i = 0; i < 16; i++) {
            float4 e = e4[i];
            dot = fmaf(xr[i].x, e.x, dot); dot = fmaf(xr[i].y, e.y, dot);
            dot = fmaf(xr[i].z, e.z, dot); dot = fmaf(xr[i].w, e.w, dot);
        }
        d1 = (xsq + g_esq[i1]) - 2.0f * dot;
    }

    // stable all-pairs rank by (d asc, idx asc); candidate indices distinct
    int rank0 = 0, rank1 = 0;
    #pragma unroll 8
    for (int s = 0; s < 32; s++) {
        float dA = __shfl_sync(0xffffffffu, d0, s); int iA = __shfl_sync(0xffffffffu, i0, s);
        float dB = __shfl_sync(0xffffffffu, d1, s); int iB = __shfl_sync(0xffffffffu, i1, s);
        rank0 += (dA < d0) || (dA == d0 && iA < i0);
        rank0 += (dB < d0) || (dB == d0 && iB < i0);
        rank1 += (dA < d1) || (dA == d1 && iA < i1);
        rank1 += (dB < d1) || (dB == d1 && iB < i1);
    }

    float topd[TOPK]; int topi[TOPK];
    #pragma unroll
    for (int j = 0; j < TOPK; j++) {
        unsigned m0 = __ballot_sync(0xffffffffu, rank0 == j);
        unsigned m1 = __ballot_sync(0xffffffffu, rank1 == j);
        int s0 = (__ffs(m0) - 1) & 31;
        int s1 = (__ffs(m1) - 1) & 31;
        float dv0 = __shfl_sync(0xffffffffu, d0, s0);
        int   iv0 = __shfl_sync(0xffffffffu, i0, s0);
        float dv1 = __shfl_sync(0xffffffffu, d1, s1);
        int   iv1 = __shfl_sync(0xffffffffu, i1, s1);
        topd[j] = m0 ? dv0 : dv1;
        topi[j] = m0 ? iv0 : iv1;
    }

    // gumbel-max over slots (strict > keeps first on ties, matches argmax)
    float gv = (lid < TOPK) ? gum[(size_t)row * TOPK + lid] : 0.f;
    float best = -__int_as_float(0x7f800000); int jb = 0;
    #pragma unroll
    for (int j = 0; j < TOPK; j++) {
        float v = __shfl_sync(0xffffffffu, gv, j) - topd[j];
        if (v > best) { best = v; jb = j; }
    }
    const int   idx  = topi[jb];
    const float mind = topd[jb];
    const bool  valid = (xsq > 1e-12f);   // norm > 1e-6
    const float vm = valid ? 1.0f : 0.0f;

    const float2* q2 = reinterpret_cast<const float2*>(cb + (size_t)idx * D_EMB);
    float2 qv = q2[lid];
    float2 x2 = reinterpret_cast<const float2*>(&sx[wid][0])[lid];
    float e0 = qv.x - x2.x, e1 = qv.y - x2.y;
    float ss = fmaf(e0, e0, e1 * e1);
    float2 o;
    o.x = x2.x + (qv.x * vm - x2.x);
    o.y = x2.y + (qv.y * vm - x2.y);
    reinterpret_cast<float2*>(out + (size_t)row * D_EMB)[lid] = o;

    ss += __shfl_xor_sync(0xffffffffu, ss, 16);
    ss += __shfl_xor_sync(0xffffffffu, ss, 8);
    ss += __shfl_xor_sync(0xffffffffu, ss, 4);
    ss += __shfl_xor_sync(0xffffffffu, ss, 2);
    ss += __shfl_xor_sync(0xffffffffu, ss, 1);
    ss *= vm;

    if (lid == 0) {
        out[OFF_IDX  + row] = valid ? (float)idx : 0.0f;
        out[OFF_MIND + row] = valid ? mind : 0.0f;
        if (valid) atomicAdd(&g_counts[idx], 1);
        sA[wid] = ss; sB[wid] = vm;
    }
    __syncthreads();
    if (tid == 0) {
        float a = 0.f, b = 0.f;
        #pragma unroll
        for (int w = 0; w < RPB2; w++) { a += sA[w]; b += sB[w]; }
        g_losspart[blockIdx.x] = a;
        g_validpart[blockIdx.x] = b;
    }
}

// ---------------------------------------------------------------------------
// final: deterministic reductions -> total_loss, perplexity (1024 threads)
// ---------------------------------------------------------------------------
__global__ __launch_bounds__(1024) void vq_final(float* __restrict__ out) {
    __shared__ float sA[1024], sB[1024];
    int tid = threadIdx.x;
    float a = 0.f, b = 0.f;
    for (int i = tid; i < GRID2; i += 1024) { a += g_losspart[i]; b += g_validpart[i]; }
    sA[tid] = a; sB[tid] = b;
    __syncthreads();
    for (int st = 512; st > 0; st >>= 1) {
        if (tid < st) { sA[tid] += sA[tid + st]; sB[tid] += sB[tid + st]; }
        __syncthreads();
    }
    float n_valid = fmaxf(sB[0], 1.0f);
    float loss_vq = sA[0] / (n_valid * (float)D_EMB);
    __syncthreads();

    float local = 0.f;
    for (int k = tid; k < K_EMB; k += 1024) {
        float p = (float)g_counts[k] / n_valid;
        local += p * logf(p + 1e-10f);
    }
    sA[tid] = local;
    __syncthreads();
    for (int st = 512; st > 0; st >>= 1) {
        if (tid < st) sA[tid] += sA[tid + st];
        __syncthreads();
    }
    if (tid == 0) {
        float perplexity = expf(-sA[0]);
        float ploss = -logf(perplexity + 1e-10f);
        out[OFF_LOSS] = loss_vq + 0.01f * ploss;
        out[OFF_PERP] = perplexity;
    }
}

extern "C" void kernel_launch(void* const* d_in, const int* in_sizes, int n_in,
                              void* d_out, int out_size) {
    (void)in_sizes; (void)n_in; (void)out_size;
    const float* inp = (const float*)d_in[0];
    const float* cb  = (const float*)d_in[1];
    const float* gum = (const float*)d_in[2];
    float* out = (float*)d_out;

    vq_prep<<<K_EMB / 32, 256>>>(cb);
    vq_pack<<<(K_EMB * (D_EMB / 2)) / 256, 256>>>(cb);
    vq_topc<<<GRID1, 256>>>(inp);
    vq_rescore<<<GRID2, 256>>>(inp, cb, gum, out);
    vq_final<<<1, 1024>>>(out);
}